// round 1
// baseline (speedup 1.0000x reference)
#include <cuda_runtime.h>

#define SQH 0.70710678118654752440f

__constant__ float c_h0o[5], c_h1o[7], c_h0a[10], c_h0b[10], c_h1a[10], c_h1b[10];

// scratch lowpass pyramids (64 planes)
__device__ float g_ll1[64u * 512u * 512u];  // 64 MB
__device__ float g_ll2[64u * 256u * 256u];  // 16 MB

__device__ __forceinline__ int refl(int p, int r) {
    if (p < 0) p = -1 - p;
    if (p >= r) p = 2 * r - 1 - p;
    return p;
}

// ---------------------------------------------------------------------------
// Level 1: biorthogonal odd filters (h0o len 5, h1o len 7), symmetric pad,
// fused row filter -> col filter -> q2c. One block = 32x64 full-res tile.
// ---------------------------------------------------------------------------
constexpr int T1W = 64, T1H = 32;

__global__ __launch_bounds__(256) void k_level1(const float* __restrict__ x,
                                                float* __restrict__ yh0) {
    __shared__ float sx[T1H + 6][T1W + 6];
    __shared__ float slo[T1H + 6][T1W];
    __shared__ float shi[T1H + 6][T1W];
    const int plane = blockIdx.z;
    const int tx0 = blockIdx.x * T1W, ty0 = blockIdx.y * T1H;
    const int tid = threadIdx.x;
    const float* xp = x + (size_t)plane * 512 * 512;

    // load x tile with halo 3 (symmetric boundary)
    for (int idx = tid; idx < (T1H + 6) * (T1W + 6); idx += 256) {
        int rr = idx / (T1W + 6), cc = idx % (T1W + 6);
        int gy = refl(ty0 - 3 + rr, 512);
        int gx = refl(tx0 - 3 + cc, 512);
        sx[rr][cc] = xp[gy * 512 + gx];
    }
    __syncthreads();

    // row (W) filter: lo = h0o (m=5,m2=2), hi = h1o (m=7,m2=3)
    for (int idx = tid; idx < (T1H + 6) * T1W; idx += 256) {
        int rr = idx / T1W, c = idx % T1W;
        float lo = 0.f, hi = 0.f;
#pragma unroll
        for (int j = 0; j < 5; ++j) lo = fmaf(c_h0o[4 - j], sx[rr][c + 1 + j], lo);
#pragma unroll
        for (int j = 0; j < 7; ++j) hi = fmaf(c_h1o[6 - j], sx[rr][c + j], hi);
        slo[rr][c] = lo;
        shi[rr][c] = hi;
    }
    __syncthreads();

    // ll = h0o col filter on lo (coalesced write to scratch)
    for (int idx = tid; idx < T1H * T1W; idx += 256) {
        int lr = idx / T1W, c = idx % T1W;
        float v = 0.f;
#pragma unroll
        for (int j = 0; j < 5; ++j) v = fmaf(c_h0o[4 - j], slo[lr + 1 + j][c], v);
        g_ll1[((size_t)plane * 512 + ty0 + lr) * 512 + tx0 + c] = v;
    }

    // lh/hl/hh col filters + q2c; each q-block is a 2x2 full-res region
    float2* yo = (float2*)yh0;
    for (int qi = tid; qi < (T1H / 2) * (T1W / 2); qi += 256) {
        int qy = qi / (T1W / 2), qx = qi % (T1W / 2);
        float lh[2][2], hl[2][2], hh[2][2];
#pragma unroll
        for (int dy = 0; dy < 2; ++dy)
#pragma unroll
            for (int dx = 0; dx < 2; ++dx) {
                int lr = 2 * qy + dy, c = 2 * qx + dx;
                float vlh = 0.f, vhl = 0.f, vhh = 0.f;
#pragma unroll
                for (int j = 0; j < 7; ++j) {
                    vlh = fmaf(c_h1o[6 - j], slo[lr + j][c], vlh);
                    vhh = fmaf(c_h1o[6 - j], shi[lr + j][c], vhh);
                }
#pragma unroll
                for (int j = 0; j < 5; ++j) vhl = fmaf(c_h0o[4 - j], shi[lr + 1 + j][c], vhl);
                lh[dy][dx] = vlh;
                hl[dy][dx] = vhl;
                hh[dy][dx] = vhh;
            }
        int gqy = (ty0 >> 1) + qy, gqx = (tx0 >> 1) + qx;
        size_t pb = (size_t)plane * 6;
        // orientation map: lh -> (0,5), hh -> (1,4), hl -> (2,3)
        yo[((pb + 0) * 256 + gqy) * 256 + gqx] =
            make_float2((lh[0][0] - lh[1][1]) * SQH, (lh[0][1] + lh[1][0]) * SQH);
        yo[((pb + 5) * 256 + gqy) * 256 + gqx] =
            make_float2((lh[0][0] + lh[1][1]) * SQH, (lh[0][1] - lh[1][0]) * SQH);
        yo[((pb + 1) * 256 + gqy) * 256 + gqx] =
            make_float2((hh[0][0] - hh[1][1]) * SQH, (hh[0][1] + hh[1][0]) * SQH);
        yo[((pb + 4) * 256 + gqy) * 256 + gqx] =
            make_float2((hh[0][0] + hh[1][1]) * SQH, (hh[0][1] - hh[1][0]) * SQH);
        yo[((pb + 2) * 256 + gqy) * 256 + gqx] =
            make_float2((hl[0][0] - hl[1][1]) * SQH, (hl[0][1] + hl[1][0]) * SQH);
        yo[((pb + 3) * 256 + gqy) * 256 + gqx] =
            make_float2((hl[0][0] + hl[1][1]) * SQH, (hl[0][1] - hl[1][0]) * SQH);
    }
}

// ---------------------------------------------------------------------------
// Levels 2/3: q-shift decimated filters (_dfilt), fused W then H + q2c.
// Output parity 0 of lowpass = ya(h0b), parity 1 = yb(h0a);
// highpass: parity 0 = yb(h1a), parity 1 = ya(h1b).
// ya offsets {-6,-8}, yb offsets {-5,-7} relative to 4*(i+j).
// ---------------------------------------------------------------------------
constexpr int T2H = 16, T2W = 32;       // half-res tile
constexpr int XR = 2 * T2H + 16;        // 48 full-res rows needed
constexpr int XC = 2 * T2W + 16;        // 80 full-res cols needed

__device__ __forceinline__ float qpair(const float* h, const float* row, int base,
                                       int offA, int offB) {
    float acc = 0.f;
#pragma unroll
    for (int j = 0; j < 5; ++j) {
        acc = fmaf(h[8 - 2 * j], row[base + 4 * j + offA], acc);
        acc = fmaf(h[9 - 2 * j], row[base + 4 * j + offB], acc);
    }
    return acc;
}

__device__ __forceinline__ float qpairS(const float* h, const float* col, int stride,
                                        int base, int offA, int offB) {
    float acc = 0.f;
#pragma unroll
    for (int j = 0; j < 5; ++j) {
        acc = fmaf(h[8 - 2 * j], col[(base + 4 * j + offA) * stride], acc);
        acc = fmaf(h[9 - 2 * j], col[(base + 4 * j + offB) * stride], acc);
    }
    return acc;
}

template <int R, int LVL>
__global__ __launch_bounds__(256) void k_dfilt(float* __restrict__ llout_arg,
                                               float* __restrict__ yh) {
    constexpr int RH = R / 2, RQ = R / 4;
    __shared__ float sx[XR][XC];
    __shared__ float slo[XR][T2W];
    __shared__ float shi[XR][T2W];
    __shared__ float sb[3][T2H][T2W];  // lh, hl, hh
    const int plane = blockIdx.z;
    const int u0 = blockIdx.x * T2W, v0 = blockIdx.y * T2H;  // half-res tile origin
    const int tid = threadIdx.x;
    const float* inp = ((LVL == 2) ? g_ll1 : g_ll2) + (size_t)plane * R * R;
    float* llout = (LVL == 2) ? (g_ll2 + (size_t)plane * RH * RH)
                              : (llout_arg + (size_t)plane * RH * RH);

    const int rawr0 = 2 * v0 - 8, rawc0 = 2 * u0 - 8;
    for (int idx = tid; idx < XR * XC; idx += 256) {
        int rr = idx / XC, cc = idx % XC;
        sx[rr][cc] = inp[(size_t)refl(rawr0 + rr, R) * R + refl(rawc0 + cc, R)];
    }
    __syncthreads();

    // W dfilt: lo_w (lowpass: h0b/h0a), hi_w (highpass: h1a/h1b)
    for (int idx = tid; idx < XR * T2W; idx += 256) {
        int rr = idx / T2W, u = idx % T2W;
        int base = 4 * (u >> 1) + 8;  // local col of 4*i, since rawc0 = 4*i0 - 8
        float lo, hi;
        if ((u & 1) == 0) {
            lo = qpair(c_h0b, sx[rr], base, -6, -8);
            hi = qpair(c_h1a, sx[rr], base, -5, -7);
        } else {
            lo = qpair(c_h0a, sx[rr], base, -5, -7);
            hi = qpair(c_h1b, sx[rr], base, -6, -8);
        }
        slo[rr][u] = lo;
        shi[rr][u] = hi;
    }
    __syncthreads();

    // H dfilt: ll/lh from lo_w, hl/hh from hi_w
    for (int idx = tid; idx < T2H * T2W; idx += 256) {
        int lv = idx / T2W, u = idx % T2W;
        int base = 4 * (lv >> 1) + 8;
        const float* cl = &slo[0][u];
        const float* ch = &shi[0][u];
        float vll, vlh, vhl, vhh;
        if ((lv & 1) == 0) {
            vll = qpairS(c_h0b, cl, T2W, base, -6, -8);
            vlh = qpairS(c_h1a, cl, T2W, base, -5, -7);
            vhl = qpairS(c_h0b, ch, T2W, base, -6, -8);
            vhh = qpairS(c_h1a, ch, T2W, base, -5, -7);
        } else {
            vll = qpairS(c_h0a, cl, T2W, base, -5, -7);
            vlh = qpairS(c_h1b, cl, T2W, base, -6, -8);
            vhl = qpairS(c_h0a, ch, T2W, base, -5, -7);
            vhh = qpairS(c_h1b, ch, T2W, base, -6, -8);
        }
        llout[(size_t)(v0 + lv) * RH + u0 + u] = vll;
        sb[0][lv][u] = vlh;
        sb[1][lv][u] = vhl;
        sb[2][lv][u] = vhh;
    }
    __syncthreads();

    // q2c on bands
    float2* yo = (float2*)yh;
    for (int qi = tid; qi < (T2H / 2) * (T2W / 2); qi += 256) {
        int qy = qi / (T2W / 2), qx = qi % (T2W / 2);
        int gqy = (v0 >> 1) + qy, gqx = (u0 >> 1) + qx;
        size_t pb = (size_t)plane * 6;
        float a, b, c, d;
        // lh -> o0, o5
        a = sb[0][2 * qy][2 * qx];     b = sb[0][2 * qy][2 * qx + 1];
        c = sb[0][2 * qy + 1][2 * qx]; d = sb[0][2 * qy + 1][2 * qx + 1];
        yo[((pb + 0) * RQ + gqy) * RQ + gqx] = make_float2((a - d) * SQH, (b + c) * SQH);
        yo[((pb + 5) * RQ + gqy) * RQ + gqx] = make_float2((a + d) * SQH, (b - c) * SQH);
        // hl -> o2, o3
        a = sb[1][2 * qy][2 * qx];     b = sb[1][2 * qy][2 * qx + 1];
        c = sb[1][2 * qy + 1][2 * qx]; d = sb[1][2 * qy + 1][2 * qx + 1];
        yo[((pb + 2) * RQ + gqy) * RQ + gqx] = make_float2((a - d) * SQH, (b + c) * SQH);
        yo[((pb + 3) * RQ + gqy) * RQ + gqx] = make_float2((a + d) * SQH, (b - c) * SQH);
        // hh -> o1, o4
        a = sb[2][2 * qy][2 * qx];     b = sb[2][2 * qy][2 * qx + 1];
        c = sb[2][2 * qy + 1][2 * qx]; d = sb[2][2 * qy + 1][2 * qx + 1];
        yo[((pb + 1) * RQ + gqy) * RQ + gqx] = make_float2((a - d) * SQH, (b + c) * SQH);
        yo[((pb + 4) * RQ + gqy) * RQ + gqx] = make_float2((a + d) * SQH, (b - c) * SQH);
    }
}

// ---------------------------------------------------------------------------
// launch
// ---------------------------------------------------------------------------
extern "C" void kernel_launch(void* const* d_in, const int* in_sizes, int n_in,
                              void* d_out, int out_size) {
    const float* x = (const float*)d_in[0];
    float* out = (float*)d_out;

    cudaMemcpyToSymbolAsync(c_h0o, d_in[1], 5 * sizeof(float), 0, cudaMemcpyDeviceToDevice, 0);
    cudaMemcpyToSymbolAsync(c_h1o, d_in[2], 7 * sizeof(float), 0, cudaMemcpyDeviceToDevice, 0);
    cudaMemcpyToSymbolAsync(c_h0a, d_in[3], 10 * sizeof(float), 0, cudaMemcpyDeviceToDevice, 0);
    cudaMemcpyToSymbolAsync(c_h0b, d_in[4], 10 * sizeof(float), 0, cudaMemcpyDeviceToDevice, 0);
    cudaMemcpyToSymbolAsync(c_h1a, d_in[5], 10 * sizeof(float), 0, cudaMemcpyDeviceToDevice, 0);
    cudaMemcpyToSymbolAsync(c_h1b, d_in[6], 10 * sizeof(float), 0, cudaMemcpyDeviceToDevice, 0);

    // float offsets into d_out: ll3 | yh0 | yh1 | yh2
    const size_t OUT_YH0 = 1048576;    // 64*128*128
    const size_t OUT_YH1 = 51380224;   // + 64*6*256*256*2
    const size_t OUT_YH2 = 63963136;   // + 64*6*128*128*2

    k_level1<<<dim3(512 / T1W, 512 / T1H, 64), 256>>>(x, out + OUT_YH0);
    k_dfilt<512, 2><<<dim3(256 / T2W, 256 / T2H, 64), 256>>>((float*)nullptr, out + OUT_YH1);
    k_dfilt<256, 3><<<dim3(128 / T2W, 128 / T2H, 64), 256>>>(out, out + OUT_YH2);
}

// round 3
// speedup vs baseline: 1.6213x; 1.6213x over previous
#include <cuda_runtime.h>

#define SQH 0.70710678118654752440f

__constant__ float c_h0o[5], c_h1o[7], c_h0a[10], c_h0b[10], c_h1a[10], c_h1b[10];

// scratch lowpass pyramids (64 planes)
__device__ float g_ll1[64u * 512u * 512u];  // 64 MB
__device__ float g_ll2[64u * 256u * 256u];  // 16 MB

__device__ __forceinline__ int refl(int p, int r) {
    if (p < 0) p = -1 - p;
    if (p >= r) p = 2 * r - 1 - p;
    return p;
}

// packed fp32x2 FMA (Blackwell): d = a*b + c per lane
__device__ __forceinline__ float2 ffma2(float2 a, float2 b, float2 c) {
    float2 d;
    asm("fma.rn.f32x2 %0, %1, %2, %3;"
        : "=l"(reinterpret_cast<unsigned long long&>(d))
        : "l"(reinterpret_cast<unsigned long long&>(a)),
          "l"(reinterpret_cast<unsigned long long&>(b)),
          "l"(reinterpret_cast<unsigned long long&>(c)));
    return d;
}
__device__ __forceinline__ float2 dup2(float v) { return make_float2(v, v); }

// ---------------------------------------------------------------------------
// Level 1: tile 32(h) x 64(w), 256 threads. Register-tiled row + col filters,
// f32x2-packed column filters (pack = two adjacent columns).
// ---------------------------------------------------------------------------
constexpr int SX1 = 76;  // sx row stride (words)
constexpr int SL1 = 66;  // slo/shi row stride (words)

__global__ __launch_bounds__(256, 3) void k_level1(const float* __restrict__ x,
                                                   float* __restrict__ yh0) {
    __shared__ float sx[38 * SX1];
    __shared__ float slo[38 * SL1];
    __shared__ float shi[38 * SL1];
    const int plane = blockIdx.z;
    const int tx0 = blockIdx.x * 64, ty0 = blockIdx.y * 32;
    const int tid = threadIdx.x;
    const float* xp = x + (size_t)plane * 262144;

    // ---- load x tile (rows ty0-3..+34, cols tx0-3..+66) ----
    if (ty0 >= 3 && ty0 + 35 <= 512 && tx0 >= 3 && tx0 + 67 <= 512) {
        const float* p0 = xp + (ty0 - 3) * 512 + (tx0 - 3);
#pragma unroll
        for (int k = 0; k < 11; ++k) {
            int idx = tid + k * 256;
            if (idx < 38 * 70) {
                int rr = idx / 70, cc = idx - rr * 70;
                sx[rr * SX1 + cc] = p0[rr * 512 + cc];
            }
        }
    } else {
        for (int idx = tid; idx < 38 * 70; idx += 256) {
            int rr = idx / 70, cc = idx - rr * 70;
            sx[rr * SX1 + cc] = xp[(size_t)refl(ty0 - 3 + rr, 512) * 512 + refl(tx0 - 3 + cc, 512)];
        }
    }
    __syncthreads();

    // ---- row filter: 38 rows x 8 chunks of 8 cols ----
    for (int idx = tid; idx < 304; idx += 256) {
        int r = idx % 38, chunk = idx / 38;
        const float* rp = &sx[r * SX1 + chunk * 8];
        float xr[16];
        ((float4*)xr)[0] = *(const float4*)rp;
        ((float4*)xr)[1] = *(const float4*)(rp + 4);
        ((float4*)xr)[2] = *(const float4*)(rp + 8);
        ((float4*)xr)[3] = *(const float4*)(rp + 12);
        float lo[8], hi[8];
#pragma unroll
        for (int k = 0; k < 8; ++k) {
            float l = 0.f, h = 0.f;
#pragma unroll
            for (int j = 0; j < 5; ++j) l = fmaf(c_h0o[4 - j], xr[k + 1 + j], l);
#pragma unroll
            for (int j = 0; j < 7; ++j) h = fmaf(c_h1o[6 - j], xr[k + j], h);
            lo[k] = l; hi[k] = h;
        }
        float* sl = &slo[r * SL1 + chunk * 8];
        float* sh = &shi[r * SL1 + chunk * 8];
#pragma unroll
        for (int k2 = 0; k2 < 4; ++k2) {
            *(float2*)&sl[2 * k2] = make_float2(lo[2 * k2], lo[2 * k2 + 1]);
            *(float2*)&sh[2 * k2] = make_float2(hi[2 * k2], hi[2 * k2 + 1]);
        }
    }
    __syncthreads();

    // ---- col filters + ll + q2c; thread = (qx, ych): 2 cols x 4 out rows ----
    const int qx = tid & 31, ych = tid >> 5;
    float2* yo = (float2*)yh0;
    const size_t pb = (size_t)plane * 6;
#pragma unroll
    for (int mi = 0; mi < 2; ++mi) {
        const int rb = 4 * ych + 2 * mi;  // local out row base (2 rows)
        float2 a[8], b[8];
#pragma unroll
        for (int k = 0; k < 8; ++k) {
            a[k] = *(const float2*)&slo[(rb + k) * SL1 + 2 * qx];
            b[k] = *(const float2*)&shi[(rb + k) * SL1 + 2 * qx];
        }
        float2 lh[2], hh[2], hl[2], ll[2];
#pragma unroll
        for (int k = 0; k < 2; ++k) {
            float2 s1 = make_float2(0.f, 0.f), s2 = s1, s3 = s1, s4 = s1;
#pragma unroll
            for (int j = 0; j < 7; ++j) {
                float2 hd = dup2(c_h1o[6 - j]);
                s1 = ffma2(hd, a[k + j], s1);
                s2 = ffma2(hd, b[k + j], s2);
            }
#pragma unroll
            for (int j = 0; j < 5; ++j) {
                float2 hd = dup2(c_h0o[4 - j]);
                s3 = ffma2(hd, b[k + 1 + j], s3);
                s4 = ffma2(hd, a[k + 1 + j], s4);
            }
            lh[k] = s1; hh[k] = s2; hl[k] = s3; ll[k] = s4;
        }
        // ll (full-res) stores
#pragma unroll
        for (int k = 0; k < 2; ++k)
            *(float2*)&g_ll1[((size_t)plane * 512 + ty0 + rb + k) * 512 + tx0 + 2 * qx] = ll[k];
        // q2c
        const int gqy = (ty0 >> 1) + 2 * ych + mi, gqx = (tx0 >> 1) + qx;
        float A, B, C, D;
        A = lh[0].x; B = lh[0].y; C = lh[1].x; D = lh[1].y;
        yo[((pb + 0) * 256 + gqy) * 256 + gqx] = make_float2((A - D) * SQH, (B + C) * SQH);
        yo[((pb + 5) * 256 + gqy) * 256 + gqx] = make_float2((A + D) * SQH, (B - C) * SQH);
        A = hh[0].x; B = hh[0].y; C = hh[1].x; D = hh[1].y;
        yo[((pb + 1) * 256 + gqy) * 256 + gqx] = make_float2((A - D) * SQH, (B + C) * SQH);
        yo[((pb + 4) * 256 + gqy) * 256 + gqx] = make_float2((A + D) * SQH, (B - C) * SQH);
        A = hl[0].x; B = hl[0].y; C = hl[1].x; D = hl[1].y;
        yo[((pb + 2) * 256 + gqy) * 256 + gqx] = make_float2((A - D) * SQH, (B + C) * SQH);
        yo[((pb + 3) * 256 + gqy) * 256 + gqx] = make_float2((A + D) * SQH, (B - C) * SQH);
    }
}

// ---------------------------------------------------------------------------
// Levels 2/3 (q-shift dfilt): tile 32x32 half-res out, 256 threads.
// W-phase register-tiled scalar; {lo,hi} stored interleaved as float2 so the
// H-phase streams rows with ffma2 computing {ll,hl} / {lh,hh} packed.
// ---------------------------------------------------------------------------
constexpr int SXD = 84;  // sx row stride (words)
constexpr int SLD = 68;  // slohi row stride (words) = 34 float2

template <int R, int LVL>
__global__ __launch_bounds__(256, 4) void k_dfilt(float* __restrict__ llout_arg,
                                                  float* __restrict__ yh) {
    constexpr int RH = R / 2, RQ = R / 4;
    __shared__ float sx[80 * SXD];
    __shared__ float slohi[80 * SLD];
    const int plane = blockIdx.z;
    const int u0 = blockIdx.x * 32, v0 = blockIdx.y * 32;
    const int tid = threadIdx.x;
    const float* inp = ((LVL == 2) ? g_ll1 : g_ll2) + (size_t)plane * R * R;
    float* llout = (LVL == 2) ? (g_ll2 + (size_t)plane * RH * RH)
                              : (llout_arg + (size_t)plane * RH * RH);
    const int rawr0 = 2 * v0 - 8, rawc0 = 2 * u0 - 8;

    // ---- load 80x80 full-res tile ----
    if (rawr0 >= 0 && rawr0 + 80 <= R && rawc0 >= 0 && rawc0 + 80 <= R) {
        const float* p0 = inp + (size_t)rawr0 * R + rawc0;
#pragma unroll
        for (int k = 0; k < 25; ++k) {
            int idx = tid + k * 256;
            int rr = idx / 80, cc = idx - rr * 80;
            sx[rr * SXD + cc] = p0[(size_t)rr * R + cc];
        }
    } else {
        for (int idx = tid; idx < 6400; idx += 256) {
            int rr = idx / 80, cc = idx - rr * 80;
            sx[rr * SXD + cc] = inp[(size_t)refl(rawr0 + rr, R) * R + refl(rawc0 + cc, R)];
        }
    }
    __syncthreads();

    // ---- W-phase dfilt: 80 rows x 4 chunks of 8 half-res cols ----
    for (int idx = tid; idx < 320; idx += 256) {
        int r = idx % 80, chunk = idx / 80;
        const float* rp = &sx[r * SXD + chunk * 16];
        float xr[32];
#pragma unroll
        for (int q = 0; q < 8; ++q) ((float4*)xr)[q] = *(const float4*)(rp + 4 * q);
        float* srow = &slohi[r * SLD + chunk * 16];
#pragma unroll
        for (int k = 0; k < 8; ++k) {
            const int r4 = 4 * (k >> 1);
            float lo = 0.f, hi = 0.f;
            if ((k & 1) == 0) {
#pragma unroll
                for (int j = 0; j < 5; ++j) {
                    lo = fmaf(c_h0b[8 - 2 * j], xr[r4 + 2 + 4 * j], lo);
                    lo = fmaf(c_h0b[9 - 2 * j], xr[r4 + 4 * j], lo);
                    hi = fmaf(c_h1a[8 - 2 * j], xr[r4 + 3 + 4 * j], hi);
                    hi = fmaf(c_h1a[9 - 2 * j], xr[r4 + 1 + 4 * j], hi);
                }
            } else {
#pragma unroll
                for (int j = 0; j < 5; ++j) {
                    lo = fmaf(c_h0a[8 - 2 * j], xr[r4 + 3 + 4 * j], lo);
                    lo = fmaf(c_h0a[9 - 2 * j], xr[r4 + 1 + 4 * j], lo);
                    hi = fmaf(c_h1b[8 - 2 * j], xr[r4 + 2 + 4 * j], hi);
                    hi = fmaf(c_h1b[9 - 2 * j], xr[r4 + 4 * j], hi);
                }
            }
            *(float2*)&srow[2 * k] = make_float2(lo, hi);
        }
    }
    __syncthreads();

    // ---- H-phase dfilt + q2c: one thread per q-point (16x16) ----
    const int qx = tid & 15, qy = tid >> 4;
    float2 accL[2][2], accH[2][2];  // {ll,hl}[parity][col], {lh,hh}[parity][col]
#pragma unroll
    for (int p = 0; p < 2; ++p)
#pragma unroll
        for (int c = 0; c < 2; ++c) {
            accL[p][c] = make_float2(0.f, 0.f);
            accH[p][c] = make_float2(0.f, 0.f);
        }
    const float* wbase = &slohi[(4 * qy) * SLD + 4 * qx];
#pragma unroll
    for (int t = 0; t < 20; ++t) {
        float4 d = *(const float4*)&wbase[t * SLD];
        float2 dA = make_float2(d.x, d.y);  // col u0: {lo, hi}
        float2 dB = make_float2(d.z, d.w);  // col u0+1
        const int j = t >> 2, tm = t & 3;
        float cl, ch;
        int pl, ph;
        if (tm == 0)      { cl = c_h0b[9 - 2 * j]; ch = c_h1b[9 - 2 * j]; pl = 0; ph = 1; }
        else if (tm == 1) { cl = c_h0a[9 - 2 * j]; ch = c_h1a[9 - 2 * j]; pl = 1; ph = 0; }
        else if (tm == 2) { cl = c_h0b[8 - 2 * j]; ch = c_h1b[8 - 2 * j]; pl = 0; ph = 1; }
        else              { cl = c_h0a[8 - 2 * j]; ch = c_h1a[8 - 2 * j]; pl = 1; ph = 0; }
        float2 cld = dup2(cl), chd = dup2(ch);
        accL[pl][0] = ffma2(cld, dA, accL[pl][0]);
        accL[pl][1] = ffma2(cld, dB, accL[pl][1]);
        accH[ph][0] = ffma2(chd, dA, accH[ph][0]);
        accH[ph][1] = ffma2(chd, dB, accH[ph][1]);
    }

    // ll stores (half-res rows v0+2qy+p)
#pragma unroll
    for (int p = 0; p < 2; ++p)
        *(float2*)&llout[(size_t)(v0 + 2 * qy + p) * RH + u0 + 2 * qx] =
            make_float2(accL[p][0].x, accL[p][1].x);

    // q2c
    float2* yo = (float2*)yh;
    const size_t pbq = (size_t)plane * 6;
    const int gqy = (v0 >> 1) + qy, gqx = (u0 >> 1) + qx;
    float A, B, C, D;
    A = accH[0][0].x; B = accH[0][1].x; C = accH[1][0].x; D = accH[1][1].x;  // lh
    yo[((pbq + 0) * RQ + gqy) * RQ + gqx] = make_float2((A - D) * SQH, (B + C) * SQH);
    yo[((pbq + 5) * RQ + gqy) * RQ + gqx] = make_float2((A + D) * SQH, (B - C) * SQH);
    A = accH[0][0].y; B = accH[0][1].y; C = accH[1][0].y; D = accH[1][1].y;  // hh
    yo[((pbq + 1) * RQ + gqy) * RQ + gqx] = make_float2((A - D) * SQH, (B + C) * SQH);
    yo[((pbq + 4) * RQ + gqy) * RQ + gqx] = make_float2((A + D) * SQH, (B - C) * SQH);
    A = accL[0][0].y; B = accL[0][1].y; C = accL[1][0].y; D = accL[1][1].y;  // hl
    yo[((pbq + 2) * RQ + gqy) * RQ + gqx] = make_float2((A - D) * SQH, (B + C) * SQH);
    yo[((pbq + 3) * RQ + gqy) * RQ + gqx] = make_float2((A + D) * SQH, (B - C) * SQH);
}

// ---------------------------------------------------------------------------
// launch
// ---------------------------------------------------------------------------
extern "C" void kernel_launch(void* const* d_in, const int* in_sizes, int n_in,
                              void* d_out, int out_size) {
    const float* x = (const float*)d_in[0];
    float* out = (float*)d_out;

    cudaMemcpyToSymbolAsync(c_h0o, d_in[1], 5 * sizeof(float), 0, cudaMemcpyDeviceToDevice, 0);
    cudaMemcpyToSymbolAsync(c_h1o, d_in[2], 7 * sizeof(float), 0, cudaMemcpyDeviceToDevice, 0);
    cudaMemcpyToSymbolAsync(c_h0a, d_in[3], 10 * sizeof(float), 0, cudaMemcpyDeviceToDevice, 0);
    cudaMemcpyToSymbolAsync(c_h0b, d_in[4], 10 * sizeof(float), 0, cudaMemcpyDeviceToDevice, 0);
    cudaMemcpyToSymbolAsync(c_h1a, d_in[5], 10 * sizeof(float), 0, cudaMemcpyDeviceToDevice, 0);
    cudaMemcpyToSymbolAsync(c_h1b, d_in[6], 10 * sizeof(float), 0, cudaMemcpyDeviceToDevice, 0);

    // float offsets into d_out: ll3 | yh0 | yh1 | yh2
    const size_t OUT_YH0 = 1048576;    // 64*128*128
    const size_t OUT_YH1 = 51380224;   // + 64*6*256*256*2
    const size_t OUT_YH2 = 63963136;   // + 64*6*128*128*2

    k_level1<<<dim3(8, 16, 64), 256>>>(x, out + OUT_YH0);
    k_dfilt<512, 2><<<dim3(8, 8, 64), 256>>>((float*)nullptr, out + OUT_YH1);
    k_dfilt<256, 3><<<dim3(4, 4, 64), 256>>>(out, out + OUT_YH2);
}